// round 16
// baseline (speedup 1.0000x reference)
#include <cuda_runtime.h>
#include <cuda_fp16.h>
#include <math.h>
#include <stdint.h>

#define Hdim   768
#define Edim   8
#define Fdim   3072
#define EFdim  (Edim * Fdim)
#define Ttok   4096
#define TKa    8192
#define TKaP   9216
#define BLKpad 16
#define MAXTILES 72

// ---------------- scratch (device globals; no allocation) ----------------
__device__ int   g_sel[TKa];
__device__ int   g_counts[Edim];
__device__ int   g_segoff[Edim];
__device__ int   g_rowTok[TKaP];
__device__ float g_rowMult[TKaP];
__device__ int   g_tileE[MAXTILES];
__device__ int   g_tileM0[MAXTILES];
__device__ int   g_nTiles;
__device__ float g_logits_scratch[Ttok * Edim];

// fp16 operand buffers (uint4-typed for 16B alignment)
__device__ uint4 g_xh_[(size_t)TKaP * Hdim / 8];    // x fp16
__device__ uint4 g_hh_[(size_t)TKaP * Fdim / 8];    // gelu(h) fp16
__device__ uint4 g_w1h_[(size_t)Hdim * EFdim / 8];  // w1 fp16 (natural [k][E*F])
__device__ uint4 g_w2h_[(size_t)EFdim * Hdim / 8];  // w2 fp16 (natural [E*F][H])
// device-code-only views (never evaluate on host!)
#define g_xh  ((unsigned short*)g_xh_)
#define g_hh  ((unsigned short*)g_hh_)
#define g_w1h ((unsigned short*)g_w1h_)
#define g_w2h ((unsigned short*)g_w2h_)

// ================= helpers =================
__device__ __forceinline__ uint32_t smem_u32(const void* p) {
    uint32_t a;
    asm("{ .reg .u64 t; cvta.to.shared.u64 t, %1; cvt.u32.u64 %0, t; }" : "=r"(a) : "l"(p));
    return a;
}
__device__ __forceinline__ float gelu_exact(float v) {
    return 0.5f * v * (1.0f + erff(v * 0.7071067811865476f));
}
__device__ __forceinline__ void cpa16(uint32_t s, const void* g) {
    asm volatile("cp.async.cg.shared.global [%0], [%1], 16;" :: "r"(s), "l"(g) : "memory");
}
__device__ __forceinline__ void ldm_x4(uint32_t* r, uint32_t addr) {
    asm volatile("ldmatrix.sync.aligned.m8n8.x4.shared.b16 {%0,%1,%2,%3}, [%4];"
                 : "=r"(r[0]), "=r"(r[1]), "=r"(r[2]), "=r"(r[3]) : "r"(addr));
}
__device__ __forceinline__ void ldm_x4t(uint32_t* r, uint32_t addr) {
    asm volatile("ldmatrix.sync.aligned.m8n8.x4.trans.shared.b16 {%0,%1,%2,%3}, [%4];"
                 : "=r"(r[0]), "=r"(r[1]), "=r"(r[2]), "=r"(r[3]) : "r"(addr));
}
__device__ __forceinline__ void mma_f16(float* d, const uint32_t* a, const uint32_t* b) {
    asm volatile("mma.sync.aligned.m16n8k16.row.col.f32.f16.f16.f32 "
                 "{%0,%1,%2,%3}, {%4,%5,%6,%7}, {%8,%9}, {%0,%1,%2,%3};"
                 : "+f"(d[0]), "+f"(d[1]), "+f"(d[2]), "+f"(d[3])
                 : "r"(a[0]), "r"(a[1]), "r"(a[2]), "r"(a[3]), "r"(b[0]), "r"(b[1]));
}
__device__ __forceinline__ unsigned pack_half2(float a, float b) {
    unsigned short h0 = __half_as_ushort(__float2half_rn(a));
    unsigned short h1 = __half_as_ushort(__float2half_rn(b));
    return (unsigned)h0 | ((unsigned)h1 << 16);
}

// ---------------- router: warp-per-token (+ zero out row) ----------------
__global__ void router_kernel(const float* __restrict__ x,
                              const float* __restrict__ rw,
                              float* __restrict__ logits_out,
                              float* __restrict__ out) {
    int warp = threadIdx.x >> 5, lane = threadIdx.x & 31;
    int t = blockIdx.x * 8 + warp;
    const float* xr = x + (size_t)t * Hdim;

    float acc[Edim];
#pragma unroll
    for (int e = 0; e < Edim; e++) acc[e] = 0.f;
#pragma unroll
    for (int j = 0; j < Hdim / 32; j++) {
        int k = lane + j * 32;
        float v = xr[k];
#pragma unroll
        for (int e = 0; e < Edim; e++) acc[e] += v * rw[e * Hdim + k];
    }
#pragma unroll
    for (int e = 0; e < Edim; e++) {
#pragma unroll
        for (int off = 16; off > 0; off >>= 1)
            acc[e] += __shfl_xor_sync(0xFFFFFFFFu, acc[e], off);
    }
    if (lane == 0) {
#pragma unroll
        for (int e = 0; e < Edim; e++) logits_out[t * Edim + e] = acc[e];
        int i0 = 0;
#pragma unroll
        for (int e = 1; e < Edim; e++) if (acc[e] > acc[i0]) i0 = e;
        int i1 = (i0 == 0) ? 1 : 0;
#pragma unroll
        for (int e = 0; e < Edim; e++) if (e != i0 && acc[e] > acc[i1]) i1 = e;
        g_sel[t * 2 + 0] = i0;
        g_sel[t * 2 + 1] = i1;
    }
    // zero this token's output row: 192 float4 spread over the warp
    float4* orow = (float4*)(out + (size_t)t * Hdim);
#pragma unroll
    for (int j = 0; j < 6; j++) orow[lane + j * 32] = make_float4(0.f, 0.f, 0.f, 0.f);
}

// ---------------- assignment: 1024 threads, smem atomics ----------------
__global__ void assign_kernel() {
    __shared__ int sCnt[Edim], sLast[Edim], sOff[Edim], sCur[Edim], sPad[Edim];
    int tid = threadIdx.x;
    if (tid < Edim) { sCnt[tid] = 0; sLast[tid] = -1; }
    for (int i = tid; i < TKaP; i += 1024) { g_rowTok[i] = -1; g_rowMult[i] = 0.f; }
    __syncthreads();
    for (int a = tid; a < TKa; a += 1024) {
        int e = g_sel[a];
        atomicAdd(&sCnt[e], 1);
        atomicMax(&sLast[e], a);
    }
    __syncthreads();
    if (tid == 0) {
        int off = 0, nt = 0;
        for (int e = 0; e < Edim; e++) {
            int c = sCnt[e];
            sOff[e] = off; sCur[e] = off;
            sPad[e] = (BLKpad - (c % BLKpad)) % BLKpad;
            g_counts[e] = c; g_segoff[e] = off;
            int ntile = (c + 127) / 128;
            for (int t = 0; t < ntile; t++) { g_tileE[nt] = e; g_tileM0[nt] = off + t * 128; nt++; }
            off += ntile * 128;
        }
        g_nTiles = nt;
    }
    __syncthreads();
    for (int a = tid; a < TKa; a += 1024) {
        int e = g_sel[a];
        int pos = atomicAdd(&sCur[e], 1);
        g_rowTok[pos] = a >> 1;
        g_rowMult[pos] = (a == sLast[e]) ? (1.0f + (float)sPad[e]) : 1.0f;
    }
}

// ---------------- gather x rows -> fp16  +  w1 -> fp16 (fused) ----------------
// blocks [0, TKaP): gather one padded row each (192 threads, float4/thread)
// blocks [TKaP, TKaP + W1BLK): convert w1, 6 float4 per thread
#define W1N4   ((size_t)Hdim * EFdim / 4)      // 4,718,592 float4
#define W1BLK  4096                             // 4096 * 192 * 6 == W1N4 exactly
__global__ void gather_kernel(const float* __restrict__ x, const float* __restrict__ w1) {
    int b = blockIdx.x;
    if (b < TKaP) {
        int tok = g_rowTok[b];
        int c4 = threadIdx.x;               // 192 threads, one float4 each
        float4 v = (tok >= 0) ? ((const float4*)(x + (size_t)tok * Hdim))[c4]
                              : make_float4(0.f, 0.f, 0.f, 0.f);
        uint2 p;
        p.x = pack_half2(v.x, v.y);
        p.y = pack_half2(v.z, v.w);
        ((uint2*)(g_xh + (size_t)b * Hdim))[c4] = p;
    } else {
        size_t base = (size_t)(b - TKaP) * (192 * 6);
        const float4* src = (const float4*)w1;
#pragma unroll
        for (int j = 0; j < 6; j++) {
            size_t i = base + (size_t)j * 192 + threadIdx.x;
            float4 v = src[i];
            uint2 p;
            p.x = pack_half2(v.x, v.y);
            p.y = pack_half2(v.z, v.w);
            ((uint2*)g_w1h)[i] = p;
        }
    }
}

// ================= grouped fp16 HMMA GEMM, 3-stage cp.async, 2 CTA/SM =================
// BM=128, BN=128, BK=16. 8 warps: warp (wm,wn) = 32x64 tile.
// MODE1 additionally converts a chunk of w2 -> fp16 (hidden under HMMA).
// MODE2 uses split-K=3 (blockIdx.z).
#define ASTRIDE 48                       // 32B data + 16B pad
#define BSTRIDE 272                      // 256B data + 16B pad
#define A_BYTES (128 * ASTRIDE)          // 6144
#define B_BYTES (16 * BSTRIDE)           // 4352
#define STAGE   (A_BYTES + B_BYTES)      // 10496: A, B
#define STAGES  3
#define SMEMSZ  (STAGES * STAGE)         // 31488

#define MMA1_GRID (Fdim / 128 * MAXTILES)   // 1728 CTAs in MODE1

template<int MODE>
__global__ void __launch_bounds__(256, 2) mma_kernel(float* __restrict__ dout,
                                                     const float* __restrict__ w2src) {
    constexpr int Kd     = (MODE == 1) ? Hdim : Fdim;
    constexpr int SPLITK = (MODE == 1) ? 1 : 3;
    constexpr int NKh    = Kd / 16 / SPLITK;     // iterations per CTA (48 / 64)

    int tid = threadIdx.x, lane = tid & 31, wid = tid >> 5;

    if (MODE == 1) {
        // convert this CTA's chunk of w2 (float4 -> 4 halves), covers all CTAs
        const size_t N2 = (size_t)EFdim * Hdim / 4;             // float4 count
        const size_t per = (N2 + MMA1_GRID - 1) / MMA1_GRID;    // ~2731
        size_t base = (size_t)(blockIdx.y * gridDim.x + blockIdx.x) * per;
        size_t end  = base + per; if (end > N2) end = N2;
        for (size_t i = base + tid; i < end; i += 256) {
            float4 v = ((const float4*)w2src)[i];
            uint2 p;
            p.x = pack_half2(v.x, v.y);
            p.y = pack_half2(v.z, v.w);
            ((uint2*)g_w2h)[i] = p;
        }
    }

    int tileIdx = blockIdx.y;
    if (tileIdx >= g_nTiles) return;
    int e  = g_tileE[tileIdx];
    int m0 = g_tileM0[tileIdx];
    int n0 = blockIdx.x * 128;
    int kbase = (SPLITK == 1) ? 0 : (int)blockIdx.z * NKh;

    extern __shared__ __align__(16) char smem[];
    uint32_t sb = smem_u32(smem);
    int wm = wid & 3, wn = wid >> 2;

    const unsigned short* aP = ((MODE == 1) ? g_xh : g_hh) + (size_t)m0 * Kd;
    const unsigned short* bP;
    size_t brs;
    if (MODE == 1) { bP = g_w1h + (size_t)e * Fdim + n0; brs = EFdim; }
    else           { bP = g_w2h + (size_t)e * Fdim * Hdim + n0; brs = Hdim; }

    // per-thread cp.async coords (one 16B chunk per buffer per thread)
    int ar = tid >> 1, ac = tid & 1;          // A: 128 rows x 2 chunks
    int br = tid >> 4, bc = tid & 15;         // B: 16 rows x 16 chunks
    uint32_t asoff = (uint32_t)(ar * ASTRIDE + ac * 16);
    uint32_t bsoff = (uint32_t)(A_BYTES + br * BSTRIDE + bc * 16);

// i = local iteration index, absolute k-chunk = kbase + i
#define ISSUE(i) do { \
        uint32_t st = sb + ((i) % STAGES) * STAGE; \
        size_t agO = (size_t)ar * Kd + (size_t)(kbase + (i)) * 16 + ac * 8; \
        size_t bgO = ((size_t)(kbase + (i)) * 16 + br) * brs + bc * 8; \
        cpa16(st + asoff, aP + agO); \
        cpa16(st + bsoff, bP + bgO); \
        asm volatile("cp.async.commit_group;" ::: "memory"); \
    } while (0)

    float acc[2][8][4];
#pragma unroll
    for (int mt = 0; mt < 2; mt++)
#pragma unroll
        for (int nt = 0; nt < 8; nt++)
#pragma unroll
            for (int i = 0; i < 4; i++) acc[mt][nt][i] = 0.f;

#pragma unroll
    for (int s = 0; s < STAGES - 1; s++) ISSUE(s);

    for (int i = 0; i < NKh; i++) {
        // tail-safe wait: when no new group is issued this iteration, drain fully
        if (i + STAGES - 1 < NKh) {
            asm volatile("cp.async.wait_group %0;" :: "n"(STAGES - 2) : "memory");
        } else {
            asm volatile("cp.async.wait_group 0;" ::: "memory");
        }
        __syncthreads();
        if (i + STAGES - 1 < NKh) ISSUE(i + STAGES - 1);

        uint32_t sA  = sb + (i % STAGES) * STAGE;
        uint32_t sBb = sA + A_BYTES;

        // load all fragments first
        uint32_t a0[2][4], bh[4][4];
#pragma unroll
        for (int mt = 0; mt < 2; mt++) {
            uint32_t ad = sA + (wm * 32 + mt * 16 + (lane & 15)) * ASTRIDE + (lane >> 4) * 16;
            ldm_x4(a0[mt], ad);
        }
#pragma unroll
        for (int ng = 0; ng < 4; ng++) {
            uint32_t bd = sBb + (lane & 15) * BSTRIDE + wn * 128 + ng * 32 + (lane >> 4) * 16;
            ldm_x4t(bh[ng], bd);
        }
        // 16 MMAs, all-distinct accumulators
#pragma unroll
        for (int ng = 0; ng < 4; ng++)
#pragma unroll
            for (int mt = 0; mt < 2; mt++)
#pragma unroll
                for (int sub = 0; sub < 2; sub++)
                    mma_f16(acc[mt][ng * 2 + sub], a0[mt], &bh[ng][sub * 2]);
    }

    // ---------------- epilogue ----------------
#pragma unroll
    for (int mt = 0; mt < 2; mt++) {
        int r0 = m0 + wm * 32 + mt * 16 + (lane >> 2);
        int r1 = r0 + 8;
        int tok0 = g_rowTok[r0], tok1 = g_rowTok[r1];
        if (MODE == 1) {
#pragma unroll
            for (int nt = 0; nt < 8; nt++) {
                int c = n0 + wn * 64 + nt * 8 + (lane & 3) * 2;
                if (tok0 >= 0) {
                    *(unsigned*)(g_hh + (size_t)r0 * Fdim + c) =
                        pack_half2(gelu_exact(acc[mt][nt][0]), gelu_exact(acc[mt][nt][1]));
                }
                if (tok1 >= 0) {
                    *(unsigned*)(g_hh + (size_t)r1 * Fdim + c) =
                        pack_half2(gelu_exact(acc[mt][nt][2]), gelu_exact(acc[mt][nt][3]));
                }
            }
        } else {
            float m0f = g_rowMult[r0], m1f = g_rowMult[r1];
#pragma unroll
            for (int nt = 0; nt < 8; nt++) {
                int c = n0 + wn * 64 + nt * 8 + (lane & 3) * 2;
                if (tok0 >= 0) {
                    float* op = dout + (size_t)tok0 * Hdim + c;
                    atomicAdd(&op[0], m0f * acc[mt][nt][0]);
                    atomicAdd(&op[1], m0f * acc[mt][nt][1]);
                }
                if (tok1 >= 0) {
                    float* op = dout + (size_t)tok1 * Hdim + c;
                    atomicAdd(&op[0], m1f * acc[mt][nt][2]);
                    atomicAdd(&op[1], m1f * acc[mt][nt][3]);
                }
            }
        }
    }
#undef ISSUE
}

// ---------------- launch ----------------
extern "C" void kernel_launch(void* const* d_in, const int* in_sizes, int n_in,
                              void* d_out, int out_size) {
    const float* x  = (const float*)d_in[0];
    const float* rw = (const float*)d_in[1];
    const float* w1 = (const float*)d_in[2];
    const float* w2 = (const float*)d_in[3];
    float* out = (float*)d_out;

    float* logits_out;
    if (out_size >= Ttok * Hdim + Ttok * Edim) {
        logits_out = out + (size_t)Ttok * Hdim;
    } else {
        void* p = nullptr;
        cudaGetSymbolAddress(&p, g_logits_scratch);
        logits_out = (float*)p;
    }

    cudaFuncSetAttribute(mma_kernel<1>, cudaFuncAttributeMaxDynamicSharedMemorySize, SMEMSZ);
    cudaFuncSetAttribute(mma_kernel<2>, cudaFuncAttributeMaxDynamicSharedMemorySize, SMEMSZ);

    router_kernel<<<Ttok / 8, 256>>>(x, rw, logits_out, out);
    assign_kernel<<<1, 1024>>>();
    gather_kernel<<<TKaP + W1BLK, 192>>>(x, w1);
    mma_kernel<1><<<dim3(Fdim / 128, MAXTILES, 1), 256, SMEMSZ>>>(nullptr, w2);
    mma_kernel<2><<<dim3(Hdim / 128, MAXTILES, 3), 256, SMEMSZ>>>(out, nullptr);
}

// round 17
// speedup vs baseline: 1.0515x; 1.0515x over previous
#include <cuda_runtime.h>
#include <cuda_fp16.h>
#include <math.h>
#include <stdint.h>

#define Hdim   768
#define Edim   8
#define Fdim   3072
#define EFdim  (Edim * Fdim)
#define Ttok   4096
#define TKa    8192
#define TKaP   9216
#define BLKpad 16
#define MAXTILES 72

// ---------------- scratch (device globals; no allocation) ----------------
__device__ int   g_sel[TKa];
__device__ int   g_counts[Edim];
__device__ int   g_segoff[Edim];
__device__ int   g_rowTok[TKaP];
__device__ float g_rowMult[TKaP];
__device__ int   g_tileE[MAXTILES];
__device__ int   g_tileM0[MAXTILES];
__device__ int   g_nTiles;
__device__ float g_logits_scratch[Ttok * Edim];

// fp16 operand buffers (uint4-typed for 16B alignment)
__device__ uint4 g_xh_[(size_t)TKaP * Hdim / 8];    // x fp16
__device__ uint4 g_hh_[(size_t)TKaP * Fdim / 8];    // gelu(h) fp16
__device__ uint4 g_w1h_[(size_t)Hdim * EFdim / 8];  // w1 fp16 (natural [k][E*F])
__device__ uint4 g_w2h_[(size_t)EFdim * Hdim / 8];  // w2 fp16 (natural [E*F][H])
// device-code-only views (never evaluate on host!)
#define g_xh  ((unsigned short*)g_xh_)
#define g_hh  ((unsigned short*)g_hh_)
#define g_w1h ((unsigned short*)g_w1h_)
#define g_w2h ((unsigned short*)g_w2h_)

// ================= helpers =================
__device__ __forceinline__ uint32_t smem_u32(const void* p) {
    uint32_t a;
    asm("{ .reg .u64 t; cvta.to.shared.u64 t, %1; cvt.u32.u64 %0, t; }" : "=r"(a) : "l"(p));
    return a;
}
__device__ __forceinline__ float gelu_exact(float v) {
    return 0.5f * v * (1.0f + erff(v * 0.7071067811865476f));
}
__device__ __forceinline__ void cpa16(uint32_t s, const void* g) {
    asm volatile("cp.async.cg.shared.global [%0], [%1], 16;" :: "r"(s), "l"(g) : "memory");
}
__device__ __forceinline__ void ldm_x4(uint32_t* r, uint32_t addr) {
    asm volatile("ldmatrix.sync.aligned.m8n8.x4.shared.b16 {%0,%1,%2,%3}, [%4];"
                 : "=r"(r[0]), "=r"(r[1]), "=r"(r[2]), "=r"(r[3]) : "r"(addr));
}
__device__ __forceinline__ void ldm_x4t(uint32_t* r, uint32_t addr) {
    asm volatile("ldmatrix.sync.aligned.m8n8.x4.trans.shared.b16 {%0,%1,%2,%3}, [%4];"
                 : "=r"(r[0]), "=r"(r[1]), "=r"(r[2]), "=r"(r[3]) : "r"(addr));
}
__device__ __forceinline__ void mma_f16(float* d, const uint32_t* a, const uint32_t* b) {
    asm volatile("mma.sync.aligned.m16n8k16.row.col.f32.f16.f16.f32 "
                 "{%0,%1,%2,%3}, {%4,%5,%6,%7}, {%8,%9}, {%0,%1,%2,%3};"
                 : "+f"(d[0]), "+f"(d[1]), "+f"(d[2]), "+f"(d[3])
                 : "r"(a[0]), "r"(a[1]), "r"(a[2]), "r"(a[3]), "r"(b[0]), "r"(b[1]));
}
__device__ __forceinline__ unsigned pack_half2(float a, float b) {
    unsigned short h0 = __half_as_ushort(__float2half_rn(a));
    unsigned short h1 = __half_as_ushort(__float2half_rn(b));
    return (unsigned)h0 | ((unsigned)h1 << 16);
}

// ---------------- router: warp-per-token (+ zero out row) ----------------
__global__ void router_kernel(const float* __restrict__ x,
                              const float* __restrict__ rw,
                              float* __restrict__ logits_out,
                              float* __restrict__ out) {
    int warp = threadIdx.x >> 5, lane = threadIdx.x & 31;
    int t = blockIdx.x * 8 + warp;
    const float* xr = x + (size_t)t * Hdim;

    float acc[Edim];
#pragma unroll
    for (int e = 0; e < Edim; e++) acc[e] = 0.f;
#pragma unroll
    for (int j = 0; j < Hdim / 32; j++) {
        int k = lane + j * 32;
        float v = xr[k];
#pragma unroll
        for (int e = 0; e < Edim; e++) acc[e] += v * rw[e * Hdim + k];
    }
#pragma unroll
    for (int e = 0; e < Edim; e++) {
#pragma unroll
        for (int off = 16; off > 0; off >>= 1)
            acc[e] += __shfl_xor_sync(0xFFFFFFFFu, acc[e], off);
    }
    if (lane == 0) {
#pragma unroll
        for (int e = 0; e < Edim; e++) logits_out[t * Edim + e] = acc[e];
        int i0 = 0;
#pragma unroll
        for (int e = 1; e < Edim; e++) if (acc[e] > acc[i0]) i0 = e;
        int i1 = (i0 == 0) ? 1 : 0;
#pragma unroll
        for (int e = 0; e < Edim; e++) if (e != i0 && acc[e] > acc[i1]) i1 = e;
        g_sel[t * 2 + 0] = i0;
        g_sel[t * 2 + 1] = i1;
    }
    // zero this token's output row: 192 float4 spread over the warp
    float4* orow = (float4*)(out + (size_t)t * Hdim);
#pragma unroll
    for (int j = 0; j < 6; j++) orow[lane + j * 32] = make_float4(0.f, 0.f, 0.f, 0.f);
}

// ---------------- assignment: 1024 threads, smem atomics ----------------
__global__ void assign_kernel() {
    __shared__ int sCnt[Edim], sLast[Edim], sOff[Edim], sCur[Edim], sPad[Edim];
    int tid = threadIdx.x;
    if (tid < Edim) { sCnt[tid] = 0; sLast[tid] = -1; }
    for (int i = tid; i < TKaP; i += 1024) { g_rowTok[i] = -1; g_rowMult[i] = 0.f; }
    __syncthreads();
    for (int a = tid; a < TKa; a += 1024) {
        int e = g_sel[a];
        atomicAdd(&sCnt[e], 1);
        atomicMax(&sLast[e], a);
    }
    __syncthreads();
    if (tid == 0) {
        int off = 0, nt = 0;
        for (int e = 0; e < Edim; e++) {
            int c = sCnt[e];
            sOff[e] = off; sCur[e] = off;
            sPad[e] = (BLKpad - (c % BLKpad)) % BLKpad;
            g_counts[e] = c; g_segoff[e] = off;
            int ntile = (c + 127) / 128;
            for (int t = 0; t < ntile; t++) { g_tileE[nt] = e; g_tileM0[nt] = off + t * 128; nt++; }
            off += ntile * 128;
        }
        g_nTiles = nt;
    }
    __syncthreads();
    for (int a = tid; a < TKa; a += 1024) {
        int e = g_sel[a];
        int pos = atomicAdd(&sCur[e], 1);
        g_rowTok[pos] = a >> 1;
        g_rowMult[pos] = (a == sLast[e]) ? (1.0f + (float)sPad[e]) : 1.0f;
    }
}

// ---------------- gather x rows -> fp16  +  w1 -> fp16 (fused) ----------------
#define W1N4   ((size_t)Hdim * EFdim / 4)      // 4,718,592 float4
#define W1BLK  4096                             // 4096 * 192 * 6 == W1N4 exactly
__global__ void gather_kernel(const float* __restrict__ x, const float* __restrict__ w1) {
    int b = blockIdx.x;
    if (b < TKaP) {
        int tok = g_rowTok[b];
        int c4 = threadIdx.x;               // 192 threads, one float4 each
        float4 v = (tok >= 0) ? ((const float4*)(x + (size_t)tok * Hdim))[c4]
                              : make_float4(0.f, 0.f, 0.f, 0.f);
        uint2 p;
        p.x = pack_half2(v.x, v.y);
        p.y = pack_half2(v.z, v.w);
        ((uint2*)(g_xh + (size_t)b * Hdim))[c4] = p;
    } else {
        size_t base = (size_t)(b - TKaP) * (192 * 6);
        const float4* src = (const float4*)w1;
#pragma unroll
        for (int j = 0; j < 6; j++) {
            size_t i = base + (size_t)j * 192 + threadIdx.x;
            float4 v = src[i];
            uint2 p;
            p.x = pack_half2(v.x, v.y);
            p.y = pack_half2(v.z, v.w);
            ((uint2*)g_w1h)[i] = p;
        }
    }
}

// ================= grouped fp16 HMMA GEMM, BK=32, 3-stage cp.async, 2 CTA/SM =================
// BM=128, BN=128, BK=32. 8 warps: warp (wm,wn) = 32x64 tile.
// One __syncthreads per 32-k (two 16-k sub-steps per iteration).
// MODE1 additionally converts a chunk of w2 -> fp16. MODE2 uses split-K=2.
#define ASTRIDE 80                       // 64B data + 16B pad
#define BSTRIDE 272                      // 256B data + 16B pad
#define A_BYTES (128 * ASTRIDE)          // 10240
#define B_BYTES (32 * BSTRIDE)           // 8704
#define STAGE   (A_BYTES + B_BYTES)      // 18944
#define STAGES  3
#define SMEMSZ  (STAGES * STAGE)         // 56832 (x2 CTA = 113664 < 228KB)

#define MMA1_GRID (Fdim / 128 * MAXTILES)   // 1728 CTAs in MODE1

template<int MODE>
__global__ void __launch_bounds__(256, 2) mma_kernel(float* __restrict__ dout,
                                                     const float* __restrict__ w2src) {
    constexpr int Kd     = (MODE == 1) ? Hdim : Fdim;
    constexpr int SPLITK = (MODE == 1) ? 1 : 2;
    constexpr int NKh    = Kd / 32 / SPLITK;     // 24 (mma1) / 48 (mma2)

    int tid = threadIdx.x, lane = tid & 31, wid = tid >> 5;

    if (MODE == 1) {
        // convert this CTA's chunk of w2 (float4 -> 4 halves), covers all CTAs
        const size_t N2 = (size_t)EFdim * Hdim / 4;             // float4 count
        const size_t per = (N2 + MMA1_GRID - 1) / MMA1_GRID;
        size_t base = (size_t)(blockIdx.y * gridDim.x + blockIdx.x) * per;
        size_t end  = base + per; if (end > N2) end = N2;
        for (size_t i = base + tid; i < end; i += 256) {
            float4 v = ((const float4*)w2src)[i];
            uint2 p;
            p.x = pack_half2(v.x, v.y);
            p.y = pack_half2(v.z, v.w);
            ((uint2*)g_w2h)[i] = p;
        }
    }

    int tileIdx = blockIdx.y;
    if (tileIdx >= g_nTiles) return;
    int e  = g_tileE[tileIdx];
    int m0 = g_tileM0[tileIdx];
    int n0 = blockIdx.x * 128;
    int kbase = (SPLITK == 1) ? 0 : (int)blockIdx.z * NKh;   // in 32-k units

    extern __shared__ __align__(16) char smem[];
    uint32_t sb = smem_u32(smem);
    int wm = wid & 3, wn = wid >> 2;

    const unsigned short* aP = ((MODE == 1) ? g_xh : g_hh) + (size_t)m0 * Kd;
    const unsigned short* bP;
    size_t brs;
    if (MODE == 1) { bP = g_w1h + (size_t)e * Fdim + n0; brs = EFdim; }
    else           { bP = g_w2h + (size_t)e * Fdim * Hdim + n0; brs = Hdim; }

    // cp.async coords: A 128r x 4 chunks (512), B 32r x 16 chunks (512); 2 each/thread
    int ar0 = tid >> 2,          ac0 = tid & 3;
    int ar1 = (tid + 256) >> 2,  ac1 = (tid + 256) & 3;
    int br0 = tid >> 4,          bc0 = tid & 15;
    int br1 = (tid + 256) >> 4,  bc1 = (tid + 256) & 15;
    uint32_t as0 = (uint32_t)(ar0 * ASTRIDE + ac0 * 16);
    uint32_t as1 = (uint32_t)(ar1 * ASTRIDE + ac1 * 16);
    uint32_t bs0 = (uint32_t)(A_BYTES + br0 * BSTRIDE + bc0 * 16);
    uint32_t bs1 = (uint32_t)(A_BYTES + br1 * BSTRIDE + bc1 * 16);

// i = local iteration index (32-k chunks), absolute = kbase + i
#define ISSUE(i) do { \
        uint32_t st = sb + ((i) % STAGES) * STAGE; \
        size_t kofs = (size_t)(kbase + (i)) * 32; \
        cpa16(st + as0, aP + (size_t)ar0 * Kd + kofs + ac0 * 8); \
        cpa16(st + as1, aP + (size_t)ar1 * Kd + kofs + ac1 * 8); \
        cpa16(st + bs0, bP + (kofs + br0) * brs + bc0 * 8); \
        cpa16(st + bs1, bP + (kofs + br1) * brs + bc1 * 8); \
        asm volatile("cp.async.commit_group;" ::: "memory"); \
    } while (0)

    float acc[2][8][4];
#pragma unroll
    for (int mt = 0; mt < 2; mt++)
#pragma unroll
        for (int nt = 0; nt < 8; nt++)
#pragma unroll
            for (int i = 0; i < 4; i++) acc[mt][nt][i] = 0.f;

#pragma unroll
    for (int s = 0; s < STAGES - 1; s++) ISSUE(s);

    for (int i = 0; i < NKh; i++) {
        // tail-safe wait: when no new group is issued this iteration, drain fully
        if (i + STAGES - 1 < NKh) {
            asm volatile("cp.async.wait_group %0;" :: "n"(STAGES - 2) : "memory");
        } else {
            asm volatile("cp.async.wait_group 0;" ::: "memory");
        }
        __syncthreads();
        if (i + STAGES - 1 < NKh) ISSUE(i + STAGES - 1);

        uint32_t sA  = sb + (i % STAGES) * STAGE;
        uint32_t sBb = sA + A_BYTES;

#pragma unroll
        for (int ks = 0; ks < 2; ks++) {
            uint32_t a0[2][4], bh[4][4];
#pragma unroll
            for (int mt = 0; mt < 2; mt++) {
                uint32_t ad = sA + (wm * 32 + mt * 16 + (lane & 15)) * ASTRIDE
                            + ks * 32 + (lane >> 4) * 16;
                ldm_x4(a0[mt], ad);
            }
#pragma unroll
            for (int ng = 0; ng < 4; ng++) {
                uint32_t bd = sBb + (ks * 16 + (lane & 15)) * BSTRIDE
                            + wn * 128 + ng * 32 + (lane >> 4) * 16;
                ldm_x4t(bh[ng], bd);
            }
#pragma unroll
            for (int ng = 0; ng < 4; ng++)
#pragma unroll
                for (int mt = 0; mt < 2; mt++)
#pragma unroll
                    for (int sub = 0; sub < 2; sub++)
                        mma_f16(acc[mt][ng * 2 + sub], a0[mt], &bh[ng][sub * 2]);
        }
    }

    // ---------------- epilogue ----------------
#pragma unroll
    for (int mt = 0; mt < 2; mt++) {
        int r0 = m0 + wm * 32 + mt * 16 + (lane >> 2);
        int r1 = r0 + 8;
        int tok0 = g_rowTok[r0], tok1 = g_rowTok[r1];
        if (MODE == 1) {
#pragma unroll
            for (int nt = 0; nt < 8; nt++) {
                int c = n0 + wn * 64 + nt * 8 + (lane & 3) * 2;
                if (tok0 >= 0) {
                    *(unsigned*)(g_hh + (size_t)r0 * Fdim + c) =
                        pack_half2(gelu_exact(acc[mt][nt][0]), gelu_exact(acc[mt][nt][1]));
                }
                if (tok1 >= 0) {
                    *(unsigned*)(g_hh + (size_t)r1 * Fdim + c) =
                        pack_half2(gelu_exact(acc[mt][nt][2]), gelu_exact(acc[mt][nt][3]));
                }
            }
        } else {
            float m0f = g_rowMult[r0], m1f = g_rowMult[r1];
#pragma unroll
            for (int nt = 0; nt < 8; nt++) {
                int c = n0 + wn * 64 + nt * 8 + (lane & 3) * 2;
                if (tok0 >= 0) {
                    float* op = dout + (size_t)tok0 * Hdim + c;
                    atomicAdd(&op[0], m0f * acc[mt][nt][0]);
                    atomicAdd(&op[1], m0f * acc[mt][nt][1]);
                }
                if (tok1 >= 0) {
                    float* op = dout + (size_t)tok1 * Hdim + c;
                    atomicAdd(&op[0], m1f * acc[mt][nt][2]);
                    atomicAdd(&op[1], m1f * acc[mt][nt][3]);
                }
            }
        }
    }
#undef ISSUE
}

// ---------------- launch ----------------
extern "C" void kernel_launch(void* const* d_in, const int* in_sizes, int n_in,
                              void* d_out, int out_size) {
    const float* x  = (const float*)d_in[0];
    const float* rw = (const float*)d_in[1];
    const float* w1 = (const float*)d_in[2];
    const float* w2 = (const float*)d_in[3];
    float* out = (float*)d_out;

    float* logits_out;
    if (out_size >= Ttok * Hdim + Ttok * Edim) {
        logits_out = out + (size_t)Ttok * Hdim;
    } else {
        void* p = nullptr;
        cudaGetSymbolAddress(&p, g_logits_scratch);
        logits_out = (float*)p;
    }

    cudaFuncSetAttribute(mma_kernel<1>, cudaFuncAttributeMaxDynamicSharedMemorySize, SMEMSZ);
    cudaFuncSetAttribute(mma_kernel<2>, cudaFuncAttributeMaxDynamicSharedMemorySize, SMEMSZ);

    router_kernel<<<Ttok / 8, 256>>>(x, rw, logits_out, out);
    assign_kernel<<<1, 1024>>>();
    gather_kernel<<<TKaP + W1BLK, 192>>>(x, w1);
    mma_kernel<1><<<dim3(Fdim / 128, MAXTILES, 1), 256, SMEMSZ>>>(nullptr, w2);
    mma_kernel<2><<<dim3(Hdim / 128, MAXTILES, 2), 256, SMEMSZ>>>(out, nullptr);
}